// round 16
// baseline (speedup 1.0000x reference)
#include <cuda_runtime.h>
#include <math.h>

#define FULL 0xFFFFFFFFu
typedef unsigned long long ull;

constexpr int B  = 64;
constexpr int P  = 4096;
constexpr int W  = 16;
constexpr int D  = 128;
constexpr int Dw = 64;

// W1r: (D, D+4) row-major, stride 132.  W1t: (D, 2*Dw+2) row-major, stride 130.

__device__ float g_src[W * D];
__device__ float g_tgt[W * D];
__device__ float g_emb[P * D];

// ---- f32x2 packed helpers ----
__device__ __forceinline__ ull pk2(float a, float b) {
    ull r; asm("mov.b64 %0, {%1, %2};" : "=l"(r) : "f"(a), "f"(b)); return r;
}
__device__ __forceinline__ void upk2(ull d, float& a, float& b) {
    asm("mov.b64 {%0, %1}, %2;" : "=f"(a), "=f"(b) : "l"(d));
}
__device__ __forceinline__ ull fma2(ull a, ull b, ull c) {
    ull d; asm("fma.rn.f32x2 %0, %1, %2, %3;" : "=l"(d) : "l"(a), "l"(b), "l"(c)); return d;
}
__device__ __forceinline__ ull add2(ull a, ull b) {
    ull d; asm("add.rn.f32x2 %0, %1, %2;" : "=l"(d) : "l"(a), "l"(b)); return d;
}

// 4-way batched warp reduction (6 shuffles for 4 sums).
// lane group j = ((lane>>4)&1) | ((lane>>2)&2) holds total of s_j.
__device__ __forceinline__ float fold4(float s0, float s1, float s2, float s3) {
    bool hi16 = (threadIdx.x & 16) != 0;
    bool hi8  = (threadIdx.x & 8) != 0;
    float a   = hi16 ? s0 : s1;
    float v01 = (hi16 ? s1 : s0) + __shfl_xor_sync(FULL, a, 16);
    float b   = hi16 ? s2 : s3;
    float v23 = (hi16 ? s3 : s2) + __shfl_xor_sync(FULL, b, 16);
    float c   = hi8 ? v01 : v23;
    float vv  = (hi8 ? v23 : v01) + __shfl_xor_sync(FULL, c, 8);
    vv += __shfl_xor_sync(FULL, vv, 4);
    vv += __shfl_xor_sync(FULL, vv, 2);
    vv += __shfl_xor_sync(FULL, vv, 1);
    return vv;
}

// ---------------------------------------------------------------------------
// k_srctgt: 8 blocks x 256 — src/tgt pair-term mini-GEMMs
// ---------------------------------------------------------------------------
__global__ void k_srctgt(const float* __restrict__ wh_emb,
                         const float* __restrict__ W1t,
                         const float* __restrict__ b1t) {
    int bid = blockIdx.x, tid = threadIdx.x;
    #pragma unroll
    for (int r = 0; r < 2; r++) {
        int idx = bid * 512 + r * 256 + tid;   // 0..4095
        int arr = idx >> 11;
        int rem = idx & 2047;
        int s = rem >> 7, d = rem & 127;
        const float* wrow = wh_emb + s * Dw;
        const float* wcol = W1t + d * 130 + arr * Dw;
        float acc = (arr == 0) ? b1t[d] : 0.f;
        #pragma unroll 8
        for (int k = 0; k < Dw; k++) acc = fmaf(wrow[k], wcol[k], acc);
        if (arr == 0) g_src[s * D + d] = acc;
        else          g_tgt[s * D + d] = acc;
    }
}

// ---------------------------------------------------------------------------
// k_emb: 256 blocks x 128 thr, 68KB dyn smem — 16 p/block (4 warps x 4 p),
// packed f32x2 accumulation
// ---------------------------------------------------------------------------
__global__ void k_emb(const float* __restrict__ part_emb,
                      const float* __restrict__ W1r,
                      const float* __restrict__ b1r) {
    extern __shared__ float dsm[];          // sWT[128*132] + sBias[128]
    int bid = blockIdx.x, tid = threadIdx.x;
    float* sWT   = dsm;
    float* sBias = dsm + 128 * 132;
    for (int i = tid; i < 128 * 128; i += 128) {
        int d = i >> 7, k = i & 127;
        sWT[k * 132 + d] = W1r[d * 132 + k];
    }
    if (tid < 128) sBias[tid] = b1r[tid] + 0.95f * W1r[tid * 132 + 130];
    __syncthreads();

    int w = tid >> 5, lane = tid & 31;
    int p0 = bid * 16 + w * 4;
    const float4* e0 = (const float4*)(part_emb + (p0 + 0) * D);
    const float4* e1 = (const float4*)(part_emb + (p0 + 1) * D);
    const float4* e2 = (const float4*)(part_emb + (p0 + 2) * D);
    const float4* e3 = (const float4*)(part_emb + (p0 + 3) * D);
    ulonglong2 bias = ((const ulonglong2*)sBias)[lane];
    ulonglong2 A0 = bias, A1 = bias, A2 = bias, A3 = bias;   // [d01, d23] per p

    #pragma unroll 4
    for (int k4 = 0; k4 < 32; k4++) {
        const float* wt = sWT + k4 * 4 * 132;
        ulonglong2 w0 = ((const ulonglong2*)(wt))[lane];
        ulonglong2 w1 = ((const ulonglong2*)(wt + 132))[lane];
        ulonglong2 w2 = ((const ulonglong2*)(wt + 264))[lane];
        ulonglong2 w3 = ((const ulonglong2*)(wt + 396))[lane];
        float4 ea = __ldg(&e0[k4]);
        float4 eb = __ldg(&e1[k4]);
        float4 ec = __ldg(&e2[k4]);
        float4 ed = __ldg(&e3[k4]);
        #define ACC2(A, E) { \
            ull ex = pk2(E.x, E.x), ey = pk2(E.y, E.y); \
            ull ez = pk2(E.z, E.z), ew = pk2(E.w, E.w); \
            A.x = fma2(ex, w0.x, fma2(ey, w1.x, fma2(ez, w2.x, fma2(ew, w3.x, A.x)))); \
            A.y = fma2(ex, w0.y, fma2(ey, w1.y, fma2(ez, w2.y, fma2(ew, w3.y, A.y)))); \
        }
        ACC2(A0, ea) ACC2(A1, eb) ACC2(A2, ec) ACC2(A3, ed)
        #undef ACC2
    }
    ((ulonglong2*)(g_emb + (p0 + 0) * D))[lane] = A0;
    ((ulonglong2*)(g_emb + (p0 + 1) * D))[lane] = A1;
    ((ulonglong2*)(g_emb + (p0 + 2) * D))[lane] = A2;
    ((ulonglong2*)(g_emb + (p0 + 3) * D))[lane] = A3;
}

// ---------------------------------------------------------------------------
// k_transfer: 1024 blocks x 256 (4 p / block), packed f32x2 inner loop
// ---------------------------------------------------------------------------
__global__ void __launch_bounds__(256, 5)
k_transfer(const float* __restrict__ wstk,
           const float* __restrict__ wdem,
           const float* __restrict__ W1t,
           const float* __restrict__ W2t,
           const float* __restrict__ b2t,
           float* __restrict__ outT) {
    __shared__ float sSrc[W * D];
    __shared__ float sTgt[W * D];
    __shared__ float sWs[D], sWd[D], sV[D];
    __shared__ float sRes[256 * 5];
    __shared__ float sSv[4 * 17];
    __shared__ int   sPl[4 * 17];
    __shared__ int   sTl[4 * 17];

    int tid = threadIdx.x;
    int bid = blockIdx.x;
    int w = tid >> 5, lane = tid & 31;
    int jm = ((lane >> 4) & 1) | ((lane >> 2) & 2);

    {
        const float4* gs = (const float4*)g_src;
        const float4* gt = (const float4*)g_tgt;
        float4* ss = (float4*)sSrc;
        float4* st4 = (float4*)sTgt;
        for (int i = tid; i < W * D / 4; i += 256) { ss[i] = gs[i]; st4[i] = gt[i]; }
    }
    if (tid < D) {
        sWs[tid] = W1t[tid * 130 + 128];
        sWd[tid] = W1t[tid * 130 + 129];
        sV[tid]  = W2t[tid];
    }

    int pslot = w >> 1;
    int q = w & 1;
    int pbase = bid * 4;
    int p = pbase + pslot;

    float sv = 0.f;
    if (lane < W) sv = wstk[lane * P + p] - wdem[lane * P + p];
    unsigned pos = __ballot_sync(FULL, (lane < W) && (sv > 0.f));
    unsigned neg = __ballot_sync(FULL, (lane < W) && (sv < 0.f));
    int npos = __popc(pos);
    int nneg = __popc(neg);

    if (q == 0 && lane < W) {
        sSv[pslot * 17 + lane] = sv;
        unsigned bit = 1u << lane;
        if (pos & bit) sPl[pslot * 17 + __popc(pos & (bit - 1))] = lane;
        if (neg & bit) sTl[pslot * 17 + __popc(neg & (bit - 1))] = lane;
    }
    __syncthreads();

    ulonglong2 ws2 = ((const ulonglong2*)sWs)[lane];
    ulonglong2 wd2 = ((const ulonglong2*)sWd)[lane];
    ulonglong2 v2  = ((const ulonglong2*)sV)[lane];
    ull z2 = 0;

    const float* svRow = sSv + pslot * 17;
    const int*   tl    = sTl + pslot * 17;

    for (int si = q; si < npos; si += 2) {
        int s = sPl[pslot * 17 + si];
        float ssp = svRow[s];
        ull ssp2 = pk2(ssp, ssp);
        ulonglong2 sr2 = ((const ulonglong2*)(sSrc + s * D))[lane];
        ull b01 = fma2(ssp2, ws2.x, sr2.x);
        ull b23 = fma2(ssp2, ws2.y, sr2.y);
        for (int ti = 0; ti < nneg; ti += 8) {
            float sA[8];
            int tt[8];
            #pragma unroll
            for (int j = 0; j < 8; j++) {
                int idx = ti + j; if (idx > nneg - 1) idx = nneg - 1;
                int t = tl[idx];
                tt[j] = t;
                float dn = -svRow[t];
                ull dn2 = pk2(dn, dn);
                ulonglong2 tg2 = ((const ulonglong2*)(sTgt + t * D))[lane];
                ull u0 = add2(b01, fma2(dn2, wd2.x, tg2.x));
                ull u1 = add2(b23, fma2(dn2, wd2.y, tg2.y));
                float h0, h1, h2, h3;
                upk2(u0, h0, h1); upk2(u1, h2, h3);
                ull h01 = pk2(fmaxf(h0, 0.f), fmaxf(h1, 0.f));
                ull h23 = pk2(fmaxf(h2, 0.f), fmaxf(h3, 0.f));
                ull dd = fma2(h01, v2.x, fma2(h23, v2.y, z2));
                float lo, hi; upk2(dd, lo, hi);
                sA[j] = lo + hi;
            }
            float tot0 = fold4(sA[0], sA[1], sA[2], sA[3]);
            float tot1 = fold4(sA[4], sA[5], sA[6], sA[7]);
            int tm0 = (lane & 16) ? ((lane & 8) ? tt[3] : tt[1])
                                  : ((lane & 8) ? tt[2] : tt[0]);
            int tm1 = (lane & 16) ? ((lane & 8) ? tt[7] : tt[5])
                                  : ((lane & 8) ? tt[6] : tt[4]);
            if (((lane & 7) == 0) && (ti + jm < nneg))
                sRes[(s * 16 + tm0) * 5 + pslot] = tot0;
            if (((lane & 7) == 0) && (ti + 4 + jm < nneg))
                sRes[(s * 16 + tm1) * 5 + pslot] = tot1;
        }
    }
    __syncthreads();

    float b2 = b2t[0];
    for (int i = tid; i < 1024; i += 256) {
        int st = i >> 2, pw = i & 3;
        int s = st >> 4, t = st & 15;
        float svs = sSv[pw * 17 + s];
        float svt = sSv[pw * 17 + t];
        float val = 0.f;
        if (svs > 0.f && svt < 0.f) {
            float x = sRes[st * 5 + pw] + b2;
            val = fminf(svs, -svt) * __fdividef(1.f, 1.f + __expf(-x));
        }
        outT[st * P + pbase + pw] = val;
    }
}

// ---------------------------------------------------------------------------
// k_reorder: 1024 blocks x 256 (4 p / block, 2 warps per p splitting b),
// packed f32x2 inner loop
// ---------------------------------------------------------------------------
__global__ void __launch_bounds__(256, 5)
k_reorder(const float* __restrict__ cur_stock,
          const float* __restrict__ demand,
          const float* __restrict__ lead,
          const float* __restrict__ W1r,
          const float* __restrict__ W2r,
          const float* __restrict__ b2r,
          float* __restrict__ outR) {
    __shared__ float sC[4 * 128];
    __shared__ float sX[4][65];
    int tid = threadIdx.x;
    int w = tid >> 5, lane = tid & 31;
    int jm = ((lane >> 4) & 1) | ((lane >> 2) & 2);

    if (tid < 128) {
        sC[tid]       = W1r[tid * 132 + 128];
        sC[128 + tid] = W1r[tid * 132 + 129];
        sC[256 + tid] = W1r[tid * 132 + 131];
        sC[384 + tid] = W2r[tid];
    }
    __syncthreads();

    ulonglong2 c0 = ((const ulonglong2*)sC)[lane];
    ulonglong2 c1 = ((const ulonglong2*)(sC + 128))[lane];
    ulonglong2 c3 = ((const ulonglong2*)(sC + 256))[lane];
    ulonglong2 v2 = ((const ulonglong2*)(sC + 384))[lane];
    ull z2 = 0;

    int pslot = w >> 1;                 // 0..3
    int bh = (w & 1) * 32;              // b-half this warp owns
    int pbase = blockIdx.x * 4;
    int p = pbase + pslot;
    ulonglong2 e2 = ((const ulonglong2*)(g_emb + p * D))[lane];

    #pragma unroll
    for (int bq = bh; bq < bh + 32; bq += 8) {
        float sA[8];
        #pragma unroll
        for (int j = 0; j < 8; j++) {
            int item = (bq + j) * P + p;
            float df = __ldg(&demand[item]);
            float lt = __ldg(&lead[item]);
            float cs = __ldg(&cur_stock[item]);
            ull df2 = pk2(df, df), lt2 = pk2(lt, lt), cs2 = pk2(cs, cs);
            ull t0 = fma2(cs2, c3.x, fma2(lt2, c1.x, fma2(df2, c0.x, e2.x)));
            ull t1 = fma2(cs2, c3.y, fma2(lt2, c1.y, fma2(df2, c0.y, e2.y)));
            float h0, h1, h2, h3;
            upk2(t0, h0, h1); upk2(t1, h2, h3);
            ull h01 = pk2(fmaxf(h0, 0.f), fmaxf(h1, 0.f));
            ull h23 = pk2(fmaxf(h2, 0.f), fmaxf(h3, 0.f));
            ull dd = fma2(h01, v2.x, fma2(h23, v2.y, z2));
            float lo, hi; upk2(dd, lo, hi);
            sA[j] = lo + hi;
        }
        float t0f = fold4(sA[0], sA[1], sA[2], sA[3]);
        float t1f = fold4(sA[4], sA[5], sA[6], sA[7]);
        if ((lane & 7) == 0) {
            sX[pslot][bq + jm]     = t0f;
            sX[pslot][bq + 4 + jm] = t1f;
        }
    }
    __syncthreads();

    float bb = b2r[0];
    {
        int b = tid >> 2, pw = tid & 3;
        float x = sX[pw][b] + bb;
        outR[b * P + pbase + pw] = fmaxf(x, 0.f) + log1pf(__expf(-fabsf(x)));
    }
}

// ---------------------------------------------------------------------------
extern "C" void kernel_launch(void* const* d_in, const int* in_sizes, int n_in,
                              void* d_out, int out_size) {
    const float* current_stock     = (const float*)d_in[0];
    const float* demand_forecast   = (const float*)d_in[1];
    const float* lead_times        = (const float*)d_in[2];
    const float* warehouse_stocks  = (const float*)d_in[3];
    const float* warehouse_demands = (const float*)d_in[4];
    const float* part_emb          = (const float*)d_in[5];
    const float* wh_emb            = (const float*)d_in[6];
    const float* W1r               = (const float*)d_in[7];
    const float* b1r               = (const float*)d_in[8];
    const float* W2r               = (const float*)d_in[9];
    const float* b2r               = (const float*)d_in[10];
    const float* W1t               = (const float*)d_in[11];
    const float* b1t               = (const float*)d_in[12];
    const float* W2t               = (const float*)d_in[13];
    const float* b2t               = (const float*)d_in[14];

    float* out_reorder  = (float*)d_out;              // [B, P]
    float* out_transfer = (float*)d_out + B * P;      // [W, W, P]

    const int dyn = (128 * 132 + 128) * sizeof(float);   // 68096 B

    static cudaStream_t s1 = nullptr;
    static cudaEvent_t evFork = nullptr, evJoin = nullptr;
    if (!s1) {
        // first call is the uncaptured correctness run — safe to create here
        cudaStreamCreateWithFlags(&s1, cudaStreamNonBlocking);
        cudaEventCreateWithFlags(&evFork, cudaEventDisableTiming);
        cudaEventCreateWithFlags(&evJoin, cudaEventDisableTiming);
        cudaFuncSetAttribute(k_emb, cudaFuncAttributeMaxDynamicSharedMemorySize, dyn);
    }

    // fork: stream1 branch = emb -> reorder (only reorder depends on emb)
    cudaEventRecord(evFork, 0);
    cudaStreamWaitEvent(s1, evFork, 0);

    k_emb<<<256, 128, dyn, s1>>>(part_emb, W1r, b1r);

    k_srctgt<<<8, 256>>>(wh_emb, W1t, b1t);
    k_transfer<<<1024, 256>>>(warehouse_stocks, warehouse_demands,
                              W1t, W2t, b2t, out_transfer);

    k_reorder<<<1024, 256, 0, s1>>>(current_stock, demand_forecast, lead_times,
                                    W1r, W2r, b2r, out_reorder);

    // join back to the capture stream
    cudaEventRecord(evJoin, s1);
    cudaStreamWaitEvent(0, evJoin, 0);
}

// round 17
// speedup vs baseline: 1.0916x; 1.0916x over previous
#include <cuda_runtime.h>
#include <math.h>

#define FULL 0xFFFFFFFFu
typedef unsigned long long ull;

constexpr int B  = 64;
constexpr int P  = 4096;
constexpr int W  = 16;
constexpr int D  = 128;
constexpr int Dw = 64;

// W1r: (D, D+4) row-major, stride 132.  W1t: (D, 2*Dw+2) row-major, stride 130.

__device__ float g_src[W * D];
__device__ float g_tgt[W * D];
__device__ float g_emb[P * D];

// ---- f32x2 packed helpers ----
__device__ __forceinline__ ull pk2(float a, float b) {
    ull r; asm("mov.b64 %0, {%1, %2};" : "=l"(r) : "f"(a), "f"(b)); return r;
}
__device__ __forceinline__ void upk2(ull d, float& a, float& b) {
    asm("mov.b64 {%0, %1}, %2;" : "=f"(a), "=f"(b) : "l"(d));
}
__device__ __forceinline__ ull fma2(ull a, ull b, ull c) {
    ull d; asm("fma.rn.f32x2 %0, %1, %2, %3;" : "=l"(d) : "l"(a), "l"(b), "l"(c)); return d;
}
__device__ __forceinline__ ull add2(ull a, ull b) {
    ull d; asm("add.rn.f32x2 %0, %1, %2;" : "=l"(d) : "l"(a), "l"(b)); return d;
}

// 4-way batched warp reduction (6 shuffles for 4 sums).
// lane group j = ((lane>>4)&1) | ((lane>>2)&2) holds total of s_j.
__device__ __forceinline__ float fold4(float s0, float s1, float s2, float s3) {
    bool hi16 = (threadIdx.x & 16) != 0;
    bool hi8  = (threadIdx.x & 8) != 0;
    float a   = hi16 ? s0 : s1;
    float v01 = (hi16 ? s1 : s0) + __shfl_xor_sync(FULL, a, 16);
    float b   = hi16 ? s2 : s3;
    float v23 = (hi16 ? s3 : s2) + __shfl_xor_sync(FULL, b, 16);
    float c   = hi8 ? v01 : v23;
    float vv  = (hi8 ? v23 : v01) + __shfl_xor_sync(FULL, c, 8);
    vv += __shfl_xor_sync(FULL, vv, 4);
    vv += __shfl_xor_sync(FULL, vv, 2);
    vv += __shfl_xor_sync(FULL, vv, 1);
    return vv;
}

// ---------------------------------------------------------------------------
// k_srctgt: 8 blocks x 256 — src/tgt pair-term mini-GEMMs
// ---------------------------------------------------------------------------
__global__ void k_srctgt(const float* __restrict__ wh_emb,
                         const float* __restrict__ W1t,
                         const float* __restrict__ b1t) {
    int bid = blockIdx.x, tid = threadIdx.x;
    #pragma unroll
    for (int r = 0; r < 2; r++) {
        int idx = bid * 512 + r * 256 + tid;   // 0..4095
        int arr = idx >> 11;
        int rem = idx & 2047;
        int s = rem >> 7, d = rem & 127;
        const float* wrow = wh_emb + s * Dw;
        const float* wcol = W1t + d * 130 + arr * Dw;
        float acc = (arr == 0) ? b1t[d] : 0.f;
        #pragma unroll 8
        for (int k = 0; k < Dw; k++) acc = fmaf(wrow[k], wcol[k], acc);
        if (arr == 0) g_src[s * D + d] = acc;
        else          g_tgt[s * D + d] = acc;
    }
}

// ---------------------------------------------------------------------------
// k_emb: 128 blocks x 256, 68KB dyn smem — R13 version (32 p / block)
// ---------------------------------------------------------------------------
__global__ void k_emb(const float* __restrict__ part_emb,
                      const float* __restrict__ W1r,
                      const float* __restrict__ b1r) {
    extern __shared__ float dsm[];          // sWT[128*132] + sBias[128]
    int bid = blockIdx.x, tid = threadIdx.x;
    float* sWT   = dsm;
    float* sBias = dsm + 128 * 132;
    for (int i = tid; i < 128 * 128; i += 256) {
        int d = i >> 7, k = i & 127;
        sWT[k * 132 + d] = W1r[d * 132 + k];
    }
    if (tid < 128) sBias[tid] = b1r[tid] + 0.95f * W1r[tid * 132 + 130];
    __syncthreads();

    int w = tid >> 5, lane = tid & 31;
    int p0 = bid * 32 + w * 4;
    const float4* e0 = (const float4*)(part_emb + (p0 + 0) * D);
    const float4* e1 = (const float4*)(part_emb + (p0 + 1) * D);
    const float4* e2 = (const float4*)(part_emb + (p0 + 2) * D);
    const float4* e3 = (const float4*)(part_emb + (p0 + 3) * D);
    float4 bias = ((const float4*)sBias)[lane];
    float4 a0 = bias, a1 = bias, a2 = bias, a3 = bias;
    #pragma unroll 4
    for (int k4 = 0; k4 < 32; k4++) {
        const float* wt = sWT + k4 * 4 * 132;
        float4 w0 = ((const float4*)(wt))[lane];
        float4 w1 = ((const float4*)(wt + 132))[lane];
        float4 w2 = ((const float4*)(wt + 264))[lane];
        float4 w3 = ((const float4*)(wt + 396))[lane];
        float4 ea = __ldg(&e0[k4]);
        float4 eb = __ldg(&e1[k4]);
        float4 ec = __ldg(&e2[k4]);
        float4 ed = __ldg(&e3[k4]);
        #define ACC(A, E) \
            A.x = fmaf(E.x, w0.x, fmaf(E.y, w1.x, fmaf(E.z, w2.x, fmaf(E.w, w3.x, A.x)))); \
            A.y = fmaf(E.x, w0.y, fmaf(E.y, w1.y, fmaf(E.z, w2.y, fmaf(E.w, w3.y, A.y)))); \
            A.z = fmaf(E.x, w0.z, fmaf(E.y, w1.z, fmaf(E.z, w2.z, fmaf(E.w, w3.z, A.z)))); \
            A.w = fmaf(E.x, w0.w, fmaf(E.y, w1.w, fmaf(E.z, w2.w, fmaf(E.w, w3.w, A.w))));
        ACC(a0, ea) ACC(a1, eb) ACC(a2, ec) ACC(a3, ed)
        #undef ACC
    }
    ((float4*)(g_emb + (p0 + 0) * D))[lane] = a0;
    ((float4*)(g_emb + (p0 + 1) * D))[lane] = a1;
    ((float4*)(g_emb + (p0 + 2) * D))[lane] = a2;
    ((float4*)(g_emb + (p0 + 3) * D))[lane] = a3;
}

// ---------------------------------------------------------------------------
// k_transfer: 1024 blocks x 256 (4 p / block), packed f32x2 inner loop,
// remainder-aware target grouping (8-groups while >=5 remain, then one 4-group)
// ---------------------------------------------------------------------------
__global__ void __launch_bounds__(256, 5)
k_transfer(const float* __restrict__ wstk,
           const float* __restrict__ wdem,
           const float* __restrict__ W1t,
           const float* __restrict__ W2t,
           const float* __restrict__ b2t,
           float* __restrict__ outT) {
    __shared__ float sSrc[W * D];
    __shared__ float sTgt[W * D];
    __shared__ float sWs[D], sWd[D], sV[D];
    __shared__ float sRes[256 * 5];
    __shared__ float sSv[4 * 17];
    __shared__ int   sPl[4 * 17];
    __shared__ int   sTl[4 * 17];

    int tid = threadIdx.x;
    int bid = blockIdx.x;
    int w = tid >> 5, lane = tid & 31;
    int jm = ((lane >> 4) & 1) | ((lane >> 2) & 2);

    {
        const float4* gs = (const float4*)g_src;
        const float4* gt = (const float4*)g_tgt;
        float4* ss = (float4*)sSrc;
        float4* st4 = (float4*)sTgt;
        for (int i = tid; i < W * D / 4; i += 256) { ss[i] = gs[i]; st4[i] = gt[i]; }
    }
    if (tid < D) {
        sWs[tid] = W1t[tid * 130 + 128];
        sWd[tid] = W1t[tid * 130 + 129];
        sV[tid]  = W2t[tid];
    }

    int pslot = w >> 1;
    int q = w & 1;
    int pbase = bid * 4;
    int p = pbase + pslot;

    float sv = 0.f;
    if (lane < W) sv = wstk[lane * P + p] - wdem[lane * P + p];
    unsigned pos = __ballot_sync(FULL, (lane < W) && (sv > 0.f));
    unsigned neg = __ballot_sync(FULL, (lane < W) && (sv < 0.f));
    int npos = __popc(pos);
    int nneg = __popc(neg);

    if (q == 0 && lane < W) {
        sSv[pslot * 17 + lane] = sv;
        unsigned bit = 1u << lane;
        if (pos & bit) sPl[pslot * 17 + __popc(pos & (bit - 1))] = lane;
        if (neg & bit) sTl[pslot * 17 + __popc(neg & (bit - 1))] = lane;
    }
    __syncthreads();

    ulonglong2 ws2 = ((const ulonglong2*)sWs)[lane];
    ulonglong2 wd2 = ((const ulonglong2*)sWd)[lane];
    ulonglong2 v2  = ((const ulonglong2*)sV)[lane];
    ull z2 = 0;

    const float* svRow = sSv + pslot * 17;
    const int*   tl    = sTl + pslot * 17;

    for (int si = q; si < npos; si += 2) {
        int s = sPl[pslot * 17 + si];
        float ssp = svRow[s];
        ull ssp2 = pk2(ssp, ssp);
        ulonglong2 sr2 = ((const ulonglong2*)(sSrc + s * D))[lane];
        ull b01 = fma2(ssp2, ws2.x, sr2.x);
        ull b23 = fma2(ssp2, ws2.y, sr2.y);

        int ti = 0;
        // 8-target groups while at least 5 targets remain (waste <= 3)
        for (; nneg - ti >= 5; ti += 8) {
            float sA[8];
            int tt[8];
            #pragma unroll
            for (int j = 0; j < 8; j++) {
                int idx = ti + j; if (idx > nneg - 1) idx = nneg - 1;
                int t = tl[idx];
                tt[j] = t;
                float dn = -svRow[t];
                ull dn2 = pk2(dn, dn);
                ulonglong2 tg2 = ((const ulonglong2*)(sTgt + t * D))[lane];
                ull u0 = add2(b01, fma2(dn2, wd2.x, tg2.x));
                ull u1 = add2(b23, fma2(dn2, wd2.y, tg2.y));
                float h0, h1, h2, h3;
                upk2(u0, h0, h1); upk2(u1, h2, h3);
                ull h01 = pk2(fmaxf(h0, 0.f), fmaxf(h1, 0.f));
                ull h23 = pk2(fmaxf(h2, 0.f), fmaxf(h3, 0.f));
                ull dd = fma2(h01, v2.x, fma2(h23, v2.y, z2));
                float lo, hi; upk2(dd, lo, hi);
                sA[j] = lo + hi;
            }
            float tot0 = fold4(sA[0], sA[1], sA[2], sA[3]);
            float tot1 = fold4(sA[4], sA[5], sA[6], sA[7]);
            int tm0 = (lane & 16) ? ((lane & 8) ? tt[3] : tt[1])
                                  : ((lane & 8) ? tt[2] : tt[0]);
            int tm1 = (lane & 16) ? ((lane & 8) ? tt[7] : tt[5])
                                  : ((lane & 8) ? tt[6] : tt[4]);
            if (((lane & 7) == 0) && (ti + jm < nneg))
                sRes[(s * 16 + tm0) * 5 + pslot] = tot0;
            if (((lane & 7) == 0) && (ti + 4 + jm < nneg))
                sRes[(s * 16 + tm1) * 5 + pslot] = tot1;
        }
        // remainder 1..4 targets: single 4-group (one fold4)
        if (ti < nneg) {
            float sA[4];
            int tt[4];
            #pragma unroll
            for (int j = 0; j < 4; j++) {
                int idx = ti + j; if (idx > nneg - 1) idx = nneg - 1;
                int t = tl[idx];
                tt[j] = t;
                float dn = -svRow[t];
                ull dn2 = pk2(dn, dn);
                ulonglong2 tg2 = ((const ulonglong2*)(sTgt + t * D))[lane];
                ull u0 = add2(b01, fma2(dn2, wd2.x, tg2.x));
                ull u1 = add2(b23, fma2(dn2, wd2.y, tg2.y));
                float h0, h1, h2, h3;
                upk2(u0, h0, h1); upk2(u1, h2, h3);
                ull h01 = pk2(fmaxf(h0, 0.f), fmaxf(h1, 0.f));
                ull h23 = pk2(fmaxf(h2, 0.f), fmaxf(h3, 0.f));
                ull dd = fma2(h01, v2.x, fma2(h23, v2.y, z2));
                float lo, hi; upk2(dd, lo, hi);
                sA[j] = lo + hi;
            }
            float tot = fold4(sA[0], sA[1], sA[2], sA[3]);
            int tm = (lane & 16) ? ((lane & 8) ? tt[3] : tt[1])
                                 : ((lane & 8) ? tt[2] : tt[0]);
            if (((lane & 7) == 0) && (ti + jm < nneg))
                sRes[(s * 16 + tm) * 5 + pslot] = tot;
        }
    }
    __syncthreads();

    float b2 = b2t[0];
    for (int i = tid; i < 1024; i += 256) {
        int st = i >> 2, pw = i & 3;
        int s = st >> 4, t = st & 15;
        float svs = sSv[pw * 17 + s];
        float svt = sSv[pw * 17 + t];
        float val = 0.f;
        if (svs > 0.f && svt < 0.f) {
            float x = sRes[st * 5 + pw] + b2;
            val = fminf(svs, -svt) * __fdividef(1.f, 1.f + __expf(-x));
        }
        outT[st * P + pbase + pw] = val;
    }
}

// ---------------------------------------------------------------------------
// k_reorder: 1024 blocks x 256 (4 p / block, 2 warps per p splitting b),
// packed f32x2 inner loop
// ---------------------------------------------------------------------------
__global__ void __launch_bounds__(256, 5)
k_reorder(const float* __restrict__ cur_stock,
          const float* __restrict__ demand,
          const float* __restrict__ lead,
          const float* __restrict__ W1r,
          const float* __restrict__ W2r,
          const float* __restrict__ b2r,
          float* __restrict__ outR) {
    __shared__ float sC[4 * 128];
    __shared__ float sX[4][65];
    int tid = threadIdx.x;
    int w = tid >> 5, lane = tid & 31;
    int jm = ((lane >> 4) & 1) | ((lane >> 2) & 2);

    if (tid < 128) {
        sC[tid]       = W1r[tid * 132 + 128];
        sC[128 + tid] = W1r[tid * 132 + 129];
        sC[256 + tid] = W1r[tid * 132 + 131];
        sC[384 + tid] = W2r[tid];
    }
    __syncthreads();

    ulonglong2 c0 = ((const ulonglong2*)sC)[lane];
    ulonglong2 c1 = ((const ulonglong2*)(sC + 128))[lane];
    ulonglong2 c3 = ((const ulonglong2*)(sC + 256))[lane];
    ulonglong2 v2 = ((const ulonglong2*)(sC + 384))[lane];
    ull z2 = 0;

    int pslot = w >> 1;                 // 0..3
    int bh = (w & 1) * 32;              // b-half this warp owns
    int pbase = blockIdx.x * 4;
    int p = pbase + pslot;
    ulonglong2 e2 = ((const ulonglong2*)(g_emb + p * D))[lane];

    #pragma unroll
    for (int bq = bh; bq < bh + 32; bq += 8) {
        float sA[8];
        #pragma unroll
        for (int j = 0; j < 8; j++) {
            int item = (bq + j) * P + p;
            float df = __ldg(&demand[item]);
            float lt = __ldg(&lead[item]);
            float cs = __ldg(&cur_stock[item]);
            ull df2 = pk2(df, df), lt2 = pk2(lt, lt), cs2 = pk2(cs, cs);
            ull t0 = fma2(cs2, c3.x, fma2(lt2, c1.x, fma2(df2, c0.x, e2.x)));
            ull t1 = fma2(cs2, c3.y, fma2(lt2, c1.y, fma2(df2, c0.y, e2.y)));
            float h0, h1, h2, h3;
            upk2(t0, h0, h1); upk2(t1, h2, h3);
            ull h01 = pk2(fmaxf(h0, 0.f), fmaxf(h1, 0.f));
            ull h23 = pk2(fmaxf(h2, 0.f), fmaxf(h3, 0.f));
            ull dd = fma2(h01, v2.x, fma2(h23, v2.y, z2));
            float lo, hi; upk2(dd, lo, hi);
            sA[j] = lo + hi;
        }
        float t0f = fold4(sA[0], sA[1], sA[2], sA[3]);
        float t1f = fold4(sA[4], sA[5], sA[6], sA[7]);
        if ((lane & 7) == 0) {
            sX[pslot][bq + jm]     = t0f;
            sX[pslot][bq + 4 + jm] = t1f;
        }
    }
    __syncthreads();

    float bb = b2r[0];
    {
        int b = tid >> 2, pw = tid & 3;
        float x = sX[pw][b] + bb;
        outR[b * P + pbase + pw] = fmaxf(x, 0.f) + log1pf(__expf(-fabsf(x)));
    }
}

// ---------------------------------------------------------------------------
extern "C" void kernel_launch(void* const* d_in, const int* in_sizes, int n_in,
                              void* d_out, int out_size) {
    const float* current_stock     = (const float*)d_in[0];
    const float* demand_forecast   = (const float*)d_in[1];
    const float* lead_times        = (const float*)d_in[2];
    const float* warehouse_stocks  = (const float*)d_in[3];
    const float* warehouse_demands = (const float*)d_in[4];
    const float* part_emb          = (const float*)d_in[5];
    const float* wh_emb            = (const float*)d_in[6];
    const float* W1r               = (const float*)d_in[7];
    const float* b1r               = (const float*)d_in[8];
    const float* W2r               = (const float*)d_in[9];
    const float* b2r               = (const float*)d_in[10];
    const float* W1t               = (const float*)d_in[11];
    const float* b1t               = (const float*)d_in[12];
    const float* W2t               = (const float*)d_in[13];
    const float* b2t               = (const float*)d_in[14];

    float* out_reorder  = (float*)d_out;              // [B, P]
    float* out_transfer = (float*)d_out + B * P;      // [W, W, P]

    const int dyn = (128 * 132 + 128) * sizeof(float);   // 68096 B

    static cudaStream_t s1 = nullptr;
    static cudaEvent_t evFork = nullptr, evJoin = nullptr;
    if (!s1) {
        // first call is the uncaptured correctness run — safe to create here
        cudaStreamCreateWithFlags(&s1, cudaStreamNonBlocking);
        cudaEventCreateWithFlags(&evFork, cudaEventDisableTiming);
        cudaEventCreateWithFlags(&evJoin, cudaEventDisableTiming);
        cudaFuncSetAttribute(k_emb, cudaFuncAttributeMaxDynamicSharedMemorySize, dyn);
    }

    // fork: stream1 branch = emb -> reorder (only reorder depends on emb)
    cudaEventRecord(evFork, 0);
    cudaStreamWaitEvent(s1, evFork, 0);

    k_emb<<<128, 256, dyn, s1>>>(part_emb, W1r, b1r);

    k_srctgt<<<8, 256>>>(wh_emb, W1t, b1t);
    k_transfer<<<1024, 256>>>(warehouse_stocks, warehouse_demands,
                              W1t, W2t, b2t, out_transfer);

    k_reorder<<<1024, 256, 0, s1>>>(current_stock, demand_forecast, lead_times,
                                    W1r, W2r, b2r, out_reorder);

    // join back to the capture stream
    cudaEventRecord(evJoin, s1);
    cudaStreamWaitEvent(0, evJoin, 0);
}